// round 5
// baseline (speedup 1.0000x reference)
#include <cuda_runtime.h>
#include <cstdint>

#define BB 16384
#define TT 2048

// Scratch: x transposed to [T, B] so the GRU kernel's per-step load is coalesced.
__device__ float g_xT[(size_t)BB * (size_t)TT];

typedef unsigned long long ull;

__device__ __forceinline__ ull pk2(float a, float b) {
    ull r; asm("mov.b64 %0, {%1, %2};" : "=l"(r) : "f"(a), "f"(b)); return r;
}
__device__ __forceinline__ void upk2(ull v, float& a, float& b) {
    asm("mov.b64 {%0, %1}, %2;" : "=f"(a), "=f"(b) : "l"(v));
}
__device__ __forceinline__ ull ffma2(ull a, ull b, ull c) {
    ull d; asm("fma.rn.f32x2 %0, %1, %2, %3;" : "=l"(d) : "l"(a), "l"(b), "l"(c)); return d;
}
// MUFU.TANH — single-instruction tanh (sm_75+)
__device__ __forceinline__ float tanh_mufu(float x) {
    float y; asm("tanh.approx.f32 %0, %1;" : "=f"(y) : "f"(x)); return y;
}
// sigmoid with the 0.5 input scale PRE-FOLDED into weights/biases:
// caller passes a = 0.5*(gi+gh); sigmoid = 0.5*tanh(a) + 0.5
__device__ __forceinline__ float sig_from_half(float a) {
    return fmaf(0.5f, tanh_mufu(a), 0.5f);
}

// ---------------------------------------------------------------------------
// Kernel 1: transpose x [B, T] -> g_xT [T, B]
// ---------------------------------------------------------------------------
__global__ void transpose_kernel(const float* __restrict__ x) {
    __shared__ float tile[32][33];
    int t0 = blockIdx.x * 32;
    int b0 = blockIdx.y * 32;
    int tx = threadIdx.x, ty = threadIdx.y;
#pragma unroll
    for (int i = 0; i < 4; i++) {
        tile[ty + i * 8][tx] = x[(size_t)(b0 + ty + i * 8) * TT + (t0 + tx)];
    }
    __syncthreads();
#pragma unroll
    for (int i = 0; i < 4; i++) {
        g_xT[(size_t)(t0 + ty + i * 8) * BB + (b0 + tx)] = tile[tx][ty + i * 8];
    }
}

// ---------------------------------------------------------------------------
// Kernel 2: GRU scan, 16-way hidden split, register weights, 2 pairs/thread.
//   - 16-lane group handles TWO packed batch pairs (4 elements) -> 6
//     independent FMA accumulation chains per thread in the dot phase, and
//     two independent MUFU tails that overlap.
//   - Lane j owns hidden index j; 48 f32x2 weights in registers (shared by
//     both pairs).
//   - Per-step h exchange via double-buffered SMEM (slots padded to 20 ull:
//     adjacent slots 8 banks apart -> conflict-free broadcast reads).
// ---------------------------------------------------------------------------

#define QPAD 20   // ull per pair slot

__global__ __launch_bounds__(128)
void gru_kernel(const float* __restrict__ w_ih, const float* __restrict__ w_hh,
                const float* __restrict__ b_ih, const float* __restrict__ b_hh,
                const float* __restrict__ w_fc, const float* __restrict__ b_fc,
                float* __restrict__ out)
{
    __shared__ ull hbuf[2][16][QPAD];

    int tid = threadIdx.x;
    int j   = tid & 15;                         // owned hidden index
    int gid = (blockIdx.x * 128 + tid) >> 4;    // group id: handles pairs 2gid, 2gid+1
    int sb  = (tid >> 4) * 2;                   // slot base in block (0..14, step 2)

    // --- register-resident recurrent weights (duplicated f32x2) ---
    ull wr_[16], wz_[16], wn_[16];
#pragma unroll
    for (int k = 0; k < 16; k++) {
        float a = 0.5f * __ldg(&w_hh[j * 16 + k]);          // r row, half-scaled
        float b = 0.5f * __ldg(&w_hh[(16 + j) * 16 + k]);   // z row, half-scaled
        float c = __ldg(&w_hh[(32 + j) * 16 + k]);          // n row
        wr_[k] = pk2(a, a);
        wz_[k] = pk2(b, b);
        wn_[k] = pk2(c, c);
    }

    // --- gate-input constants ---
    float wirf = 0.5f * __ldg(&w_ih[j]);
    float wizf = 0.5f * __ldg(&w_ih[16 + j]);
    float winf = __ldg(&w_ih[32 + j]);
    float bsrf = 0.5f * (__ldg(&b_ih[j]) + __ldg(&b_hh[j]));
    float bszf = 0.5f * (__ldg(&b_ih[16 + j]) + __ldg(&b_hh[16 + j]));
    float binf = __ldg(&b_ih[32 + j]);
    float bhnf = __ldg(&b_hh[32 + j]);
    ull wirp = pk2(wirf, wirf), wizp = pk2(wizf, wizf), winp = pk2(winf, winf);
    ull bsrp = pk2(bsrf, bsrf), bszp = pk2(bszf, bszf);
    ull binp = pk2(binf, binf), bhnp = pk2(bhnf, bhnf);

    ull hx0[16], hx1[16];
#pragma unroll
    for (int k = 0; k < 16; k++) { hx0[k] = 0ull; hx1[k] = 0ull; }
    ull hown0 = 0ull, hown1 = 0ull;

    // x: both pairs are 4 consecutive floats -> one float4 per step
    const float4* xp = ((const float4*)g_xT) + gid;
    float4 xv = __ldg(&xp[0]);

    int buf = 0;
    for (int t = 0; t < TT; t++) {
        ull x2a = pk2(xv.x, xv.y);
        ull x2b = pk2(xv.z, xv.w);
        int tn = (t < TT - 1) ? (t + 1) : t;
        float4 xnext = __ldg(&xp[(size_t)tn * (BB / 4)]);

        // 6 independent accumulation chains
        ull aR0 = ffma2(x2a, wirp, bsrp);
        ull aZ0 = ffma2(x2a, wizp, bszp);
        ull aN0 = bhnp;
        ull aR1 = ffma2(x2b, wirp, bsrp);
        ull aZ1 = ffma2(x2b, wizp, bszp);
        ull aN1 = bhnp;
#pragma unroll
        for (int k = 0; k < 16; k++) {
            aR0 = ffma2(wr_[k], hx0[k], aR0);
            aR1 = ffma2(wr_[k], hx1[k], aR1);
            aZ0 = ffma2(wz_[k], hx0[k], aZ0);
            aZ1 = ffma2(wz_[k], hx1[k], aZ1);
            aN0 = ffma2(wn_[k], hx0[k], aN0);
            aN1 = ffma2(wn_[k], hx1[k], aN1);
        }

        // --- tail pair 0 ---
        {
            float a0, a1; upk2(aR0, a0, a1);
            ull rr = pk2(sig_from_half(a0), sig_from_half(a1));
            float z0, z1; upk2(aZ0, z0, z1);
            z0 = sig_from_half(z0);
            z1 = sig_from_half(z1);
            ull gi  = ffma2(x2a, winp, binp);
            ull pre = ffma2(rr, aN0, gi);
            float p0, p1; upk2(pre, p0, p1);
            float n0 = tanh_mufu(p0);
            float n1 = tanh_mufu(p1);
            float h0, h1; upk2(hown0, h0, h1);
            h0 = fmaf(z0, h0 - n0, n0);
            h1 = fmaf(z1, h1 - n1, n1);
            hown0 = pk2(h0, h1);
        }
        // --- tail pair 1 (independent, overlaps) ---
        {
            float a0, a1; upk2(aR1, a0, a1);
            ull rr = pk2(sig_from_half(a0), sig_from_half(a1));
            float z0, z1; upk2(aZ1, z0, z1);
            z0 = sig_from_half(z0);
            z1 = sig_from_half(z1);
            ull gi  = ffma2(x2b, winp, binp);
            ull pre = ffma2(rr, aN1, gi);
            float p0, p1; upk2(pre, p0, p1);
            float n0 = tanh_mufu(p0);
            float n1 = tanh_mufu(p1);
            float h0, h1; upk2(hown1, h0, h1);
            h0 = fmaf(z0, h0 - n0, n0);
            h1 = fmaf(z1, h1 - n1, n1);
            hown1 = pk2(h0, h1);
        }

        // exchange both pairs, one sync
        hbuf[buf][sb][j]     = hown0;
        hbuf[buf][sb + 1][j] = hown1;
        __syncwarp();
#pragma unroll
        for (int k2 = 0; k2 < 8; k2++) {
            ulonglong2 v0 = *(const ulonglong2*)&hbuf[buf][sb][2 * k2];
            hx0[2 * k2]     = v0.x;
            hx0[2 * k2 + 1] = v0.y;
            ulonglong2 v1 = *(const ulonglong2*)&hbuf[buf][sb + 1][2 * k2];
            hx1[2 * k2]     = v1.x;
            hx1[2 * k2 + 1] = v1.y;
        }
        buf ^= 1;

        xv = xnext;
    }

    // FC epilogue: 4 outputs per group
    float wf = __ldg(&w_fc[j]);
    float h0, h1, h2, h3;
    upk2(hown0, h0, h1);
    upk2(hown1, h2, h3);
    float s0 = h0 * wf, s1 = h1 * wf, s2 = h2 * wf, s3 = h3 * wf;
#pragma unroll
    for (int d = 1; d < 16; d <<= 1) {
        s0 += __shfl_xor_sync(0xffffffffu, s0, d);
        s1 += __shfl_xor_sync(0xffffffffu, s1, d);
        s2 += __shfl_xor_sync(0xffffffffu, s2, d);
        s3 += __shfl_xor_sync(0xffffffffu, s3, d);
    }
    if (j == 0) {
        float bf = __ldg(b_fc);
        float4 o;
        o.x = s0 + bf; o.y = s1 + bf; o.z = s2 + bf; o.w = s3 + bf;
        *(float4*)(out + 4 * gid) = o;
    }
}

// ---------------------------------------------------------------------------
extern "C" void kernel_launch(void* const* d_in, const int* in_sizes, int n_in,
                              void* d_out, int out_size)
{
    const float* x    = (const float*)d_in[0];
    const float* w_ih = (const float*)d_in[1];
    const float* w_hh = (const float*)d_in[2];
    const float* b_ih = (const float*)d_in[3];
    const float* b_hh = (const float*)d_in[4];
    const float* w_fc = (const float*)d_in[5];
    const float* b_fc = (const float*)d_in[6];
    float* out = (float*)d_out;

    dim3 tb(32, 8);
    dim3 tg(TT / 32, BB / 32);
    transpose_kernel<<<tg, tb>>>(x);

    // 16384 batch / 4 per 16-lane group * 16 lanes = 65536 threads
    gru_kernel<<<512, 128>>>(w_ih, w_hh, b_ih, b_hh, w_fc, b_fc, out);
}

// round 6
// speedup vs baseline: 1.2295x; 1.2295x over previous
#include <cuda_runtime.h>
#include <cstdint>

#define BB 16384
#define TT 2048

// Scratch: x transposed to [T, B]; padded by one timestep so the prefetch of
// t+1 never branches (last prefetched value is read but never used).
__device__ float g_xT[(size_t)BB * (size_t)(TT + 1)];

typedef unsigned long long ull;

__device__ __forceinline__ ull pk2(float a, float b) {
    ull r; asm("mov.b64 %0, {%1, %2};" : "=l"(r) : "f"(a), "f"(b)); return r;
}
__device__ __forceinline__ void upk2(ull v, float& a, float& b) {
    asm("mov.b64 {%0, %1}, %2;" : "=f"(a), "=f"(b) : "l"(v));
}
__device__ __forceinline__ ull ffma2(ull a, ull b, ull c) {
    ull d; asm("fma.rn.f32x2 %0, %1, %2, %3;" : "=l"(d) : "l"(a), "l"(b), "l"(c)); return d;
}
// MUFU.TANH — single-instruction tanh (sm_75+)
__device__ __forceinline__ float tanh_mufu(float x) {
    float y; asm("tanh.approx.f32 %0, %1;" : "=f"(y) : "f"(x)); return y;
}
// sigmoid with the 0.5 input scale PRE-FOLDED into weights/biases:
// caller passes a = 0.5*(gi+gh); sigmoid = 0.5*tanh(a) + 0.5
__device__ __forceinline__ float sig_from_half(float a) {
    return fmaf(0.5f, tanh_mufu(a), 0.5f);
}

// ---------------------------------------------------------------------------
// Kernel 1: transpose x [B, T] -> g_xT [T, B]
// ---------------------------------------------------------------------------
__global__ void transpose_kernel(const float* __restrict__ x) {
    __shared__ float tile[32][33];
    int t0 = blockIdx.x * 32;
    int b0 = blockIdx.y * 32;
    int tx = threadIdx.x, ty = threadIdx.y;
#pragma unroll
    for (int i = 0; i < 4; i++) {
        tile[ty + i * 8][tx] = x[(size_t)(b0 + ty + i * 8) * TT + (t0 + tx)];
    }
    __syncthreads();
#pragma unroll
    for (int i = 0; i < 4; i++) {
        g_xT[(size_t)(t0 + ty + i * 8) * BB + (b0 + tx)] = tile[tx][ty + i * 8];
    }
}

// ---------------------------------------------------------------------------
// Kernel 2: GRU scan, 16-way hidden split, TRULY register-resident weights.
//   - 16-lane group handles one packed batch pair (f32x2 over 2 elements).
//   - Lane j owns hidden index j and gate rows {j, 16+j, 32+j}; 48 f32x2
//     weights in registers. __launch_bounds__(128,1) so ptxas does NOT spill
//     them to local (plain (128) chose 112 regs and spilled).
//   - Per-step h exchange via double-buffered SMEM (slots padded to 20 ull).
//   - r/z weights+biases pre-scaled by 0.5 (sigmoid via tanh identity).
// ---------------------------------------------------------------------------

#define QPAD 20   // ull per pair slot (16 + 4 pad -> 8-bank offset between slots)

__global__ __launch_bounds__(128, 1)
void gru_kernel(const float* __restrict__ w_ih, const float* __restrict__ w_hh,
                const float* __restrict__ b_ih, const float* __restrict__ b_hh,
                const float* __restrict__ w_fc, const float* __restrict__ b_fc,
                float* __restrict__ out)
{
    __shared__ ull hbuf[2][8][QPAD];

    int tid = threadIdx.x;
    int g   = blockIdx.x * 128 + tid;
    int j   = g & 15;          // owned hidden index
    int p   = g >> 4;          // global batch-pair index (elements 2p, 2p+1)
    int pb  = tid >> 4;        // pair slot within block (0..7)

    // --- register-resident recurrent weights (duplicated f32x2) ---
    ull wr_[16], wz_[16], wn_[16];
#pragma unroll
    for (int k = 0; k < 16; k++) {
        float a = 0.5f * __ldg(&w_hh[j * 16 + k]);          // r row, half-scaled
        float b = 0.5f * __ldg(&w_hh[(16 + j) * 16 + k]);   // z row, half-scaled
        float c = __ldg(&w_hh[(32 + j) * 16 + k]);          // n row
        wr_[k] = pk2(a, a);
        wz_[k] = pk2(b, b);
        wn_[k] = pk2(c, c);
    }

    // --- gate-input constants ---
    float wirf = 0.5f * __ldg(&w_ih[j]);
    float wizf = 0.5f * __ldg(&w_ih[16 + j]);
    float winf = __ldg(&w_ih[32 + j]);
    float bsrf = 0.5f * (__ldg(&b_ih[j]) + __ldg(&b_hh[j]));
    float bszf = 0.5f * (__ldg(&b_ih[16 + j]) + __ldg(&b_hh[16 + j]));
    float binf = __ldg(&b_ih[32 + j]);
    float bhnf = __ldg(&b_hh[32 + j]);
    ull wirp = pk2(wirf, wirf), wizp = pk2(wizf, wizf), winp = pk2(winf, winf);
    ull bsrp = pk2(bsrf, bsrf), bszp = pk2(bszf, bszf);
    ull binp = pk2(binf, binf), bhnp = pk2(bhnf, bhnf);

    // hx[k] = packed h_k for both elements; hown = own h_j
    ull hx[16];
#pragma unroll
    for (int k = 0; k < 16; k++) hx[k] = 0ull;
    ull hown = 0ull;

    const float2* xp = ((const float2*)g_xT) + p;
    float2 xv = __ldg(xp);
    xp += (BB / 2);

    int buf = 0;
    for (int t = 0; t < TT; t++) {
        ull x2 = pk2(xv.x, xv.y);
        float2 xnext = __ldg(xp);      // padded array: always valid
        xp += (BB / 2);

        // three gate pre-activations (independent FMA chains)
        ull aR = ffma2(x2, wirp, bsrp);
        ull aZ = ffma2(x2, wizp, bszp);
        ull aN = bhnp;
#pragma unroll
        for (int k = 0; k < 16; k++) {
            aR = ffma2(wr_[k], hx[k], aR);
            aZ = ffma2(wz_[k], hx[k], aZ);
            aN = ffma2(wn_[k], hx[k], aN);
        }

        float a0, a1;
        upk2(aR, a0, a1);
        ull rr = pk2(sig_from_half(a0), sig_from_half(a1));
        float z0, z1;
        upk2(aZ, z0, z1);
        z0 = sig_from_half(z0);
        z1 = sig_from_half(z1);

        ull gi  = ffma2(x2, winp, binp);
        ull pre = ffma2(rr, aN, gi);
        float p0, p1;
        upk2(pre, p0, p1);
        float n0 = tanh_mufu(p0);
        float n1 = tanh_mufu(p1);

        float h0, h1;
        upk2(hown, h0, h1);
        h0 = fmaf(z0, h0 - n0, n0);    // (1-z)n + z h
        h1 = fmaf(z1, h1 - n1, n1);
        hown = pk2(h0, h1);

        // exchange: write own h, sync, reload all 16
        hbuf[buf][pb][j] = hown;
        __syncwarp();
#pragma unroll
        for (int k2 = 0; k2 < 8; k2++) {
            ulonglong2 v = *(const ulonglong2*)&hbuf[buf][pb][2 * k2];
            hx[2 * k2]     = v.x;
            hx[2 * k2 + 1] = v.y;
        }
        buf ^= 1;

        xv = xnext;
    }

    // FC epilogue: out[b] = sum_j h[b][j] * w_fc[j] + b_fc
    float wf = __ldg(&w_fc[j]);
    float h0, h1;
    upk2(hown, h0, h1);
    float s0 = h0 * wf;
    float s1 = h1 * wf;
#pragma unroll
    for (int d = 1; d < 16; d <<= 1) {
        s0 += __shfl_xor_sync(0xffffffffu, s0, d);
        s1 += __shfl_xor_sync(0xffffffffu, s1, d);
    }
    if (j == 0) {
        float bf = __ldg(b_fc);
        float2 o;
        o.x = s0 + bf;
        o.y = s1 + bf;
        *(float2*)(out + 2 * p) = o;
    }
}

// ---------------------------------------------------------------------------
extern "C" void kernel_launch(void* const* d_in, const int* in_sizes, int n_in,
                              void* d_out, int out_size)
{
    const float* x    = (const float*)d_in[0];
    const float* w_ih = (const float*)d_in[1];
    const float* w_hh = (const float*)d_in[2];
    const float* b_ih = (const float*)d_in[3];
    const float* b_hh = (const float*)d_in[4];
    const float* w_fc = (const float*)d_in[5];
    const float* b_fc = (const float*)d_in[6];
    float* out = (float*)d_out;

    dim3 tb(32, 8);
    dim3 tg(TT / 32, BB / 32);
    transpose_kernel<<<tg, tb>>>(x);

    // 16384 batch / 2 per 16-lane group * 16 lanes = 131072 threads
    gru_kernel<<<1024, 128>>>(w_ih, w_hh, b_ih, b_hh, w_fc, b_fc, out);
}